// round 1
// baseline (speedup 1.0000x reference)
#include <cuda_runtime.h>
#include <cstdint>
#include <cstdio>

#define IN_DIM 128
#define HID    256
#define TILE_R 64

// Scratch: P_clicks[100000*256], Q_clicks[200000*256], P_buys, Q_buys
// = 153,600,000 floats = 614.4 MB. __device__ global (no runtime alloc).
#define P_ELEMS (100000u * 256u)   // 25,600,000
#define Q_ELEMS (200000u * 256u)   // 51,200,000
__device__ float g_scratch[2u * (P_ELEMS + Q_ELEMS)];

// ---------------------------------------------------------------------------
// Precompute kernel: P[r, :] = A[r, :128] @ W[:128, :256]
// One block = 64 rows x 256 cols. 256 threads, each owns an 8x8 micro-tile.
// W half (128x256 fp32 = 128KB) + A tile (64x128 fp32 = 32KB) staged in smem.
// ---------------------------------------------------------------------------
__global__ __launch_bounds__(256, 1)
void proj_kernel(const float* __restrict__ A, int N,
                 const float* __restrict__ W,   // [IN_DIM, HID] row-major
                 float* __restrict__ P) {
    extern __shared__ float sm[];
    float* As = sm;                     // TILE_R * IN_DIM
    float* Ws = sm + TILE_R * IN_DIM;   // IN_DIM * HID

    const int tid = threadIdx.x;
    const int r0  = blockIdx.x * TILE_R;

    // Stage W half (32768 floats)
    #pragma unroll 4
    for (int i = tid; i < IN_DIM * HID; i += 256) Ws[i] = W[i];

    // Stage A tile (8192 floats), zero-pad past N
    #pragma unroll 4
    for (int i = tid; i < TILE_R * IN_DIM; i += 256) {
        int r  = i >> 7;        // / IN_DIM
        int c  = i & (IN_DIM - 1);
        int rg = r0 + r;
        As[i] = (rg < N) ? A[(size_t)rg * IN_DIM + c] : 0.0f;
    }
    __syncthreads();

    const int lane = tid & 31;
    const int warp = tid >> 5;

    float acc[8][8];
    #pragma unroll
    for (int rr = 0; rr < 8; rr++)
        #pragma unroll
        for (int jj = 0; jj < 8; jj++) acc[rr][jj] = 0.0f;

    // rows: warp + 8*rr (broadcast LDS per warp); cols: lane + 32*jj (conflict-free)
    #pragma unroll 4
    for (int k = 0; k < IN_DIM; k++) {
        float a[8], w[8];
        #pragma unroll
        for (int rr = 0; rr < 8; rr++) a[rr] = As[(warp + 8 * rr) * IN_DIM + k];
        #pragma unroll
        for (int jj = 0; jj < 8; jj++) w[jj] = Ws[k * HID + lane + 32 * jj];
        #pragma unroll
        for (int rr = 0; rr < 8; rr++)
            #pragma unroll
            for (int jj = 0; jj < 8; jj++)
                acc[rr][jj] = fmaf(a[rr], w[jj], acc[rr][jj]);
    }

    #pragma unroll
    for (int rr = 0; rr < 8; rr++) {
        int r = r0 + warp + 8 * rr;
        if (r < N) {
            float* dst = P + (size_t)r * HID;
            #pragma unroll
            for (int jj = 0; jj < 8; jj++)
                dst[lane + 32 * jj] = acc[rr][jj];
        }
    }
}

// ---------------------------------------------------------------------------
// Edge kernel: one warp per edge.
// logit = sum_j relu(P[u][j] + Q[v][j] + b1[j]) * W2[j] + b2
// ---------------------------------------------------------------------------
__global__ __launch_bounds__(256)
void edge_kernel(const int* __restrict__ uidx, const int* __restrict__ vidx,
                 const float* __restrict__ P, const float* __restrict__ Q,
                 const float* __restrict__ b1, const float* __restrict__ W2,
                 const float* __restrict__ b2, float* __restrict__ out, int E) {
    const int gwarp = (blockIdx.x * blockDim.x + threadIdx.x) >> 5;
    const int lane  = threadIdx.x & 31;
    if (gwarp >= E) return;

    const int u = __ldg(uidx + gwarp);
    const int v = __ldg(vidx + gwarp);
    const float* pu = P + (size_t)u * HID;
    const float* qv = Q + (size_t)v * HID;

    float acc = 0.0f;
    #pragma unroll
    for (int s = 0; s < 8; s++) {
        int j = lane + 32 * s;
        float h = pu[j] + qv[j] + __ldg(b1 + j);
        h = fmaxf(h, 0.0f);
        acc = fmaf(h, __ldg(W2 + j), acc);
    }
    #pragma unroll
    for (int o = 16; o; o >>= 1) acc += __shfl_xor_sync(0xffffffffu, acc, o);

    if (lane == 0) out[gwarp] = acc + __ldg(b2);
}

// ---------------------------------------------------------------------------
// Launch
// ---------------------------------------------------------------------------
extern "C" void kernel_launch(void* const* d_in, const int* in_sizes, int n_in,
                              void* d_out, int out_size) {
    const float* user_embed = (const float*)d_in[0];   // [100000,128]
    const float* item_embed = (const float*)d_in[1];   // [200000,128]
    const int*   u_clicks   = (const int*)  d_in[2];   // [E]
    const int*   v_clicks   = (const int*)  d_in[3];
    const int*   u_buys     = (const int*)  d_in[4];
    const int*   v_buys     = (const int*)  d_in[5];
    const float* W1_clicks  = (const float*)d_in[6];   // [256,256]
    const float* b1_clicks  = (const float*)d_in[7];
    const float* W2_clicks  = (const float*)d_in[8];
    const float* b2_clicks  = (const float*)d_in[9];
    const float* W1_buys    = (const float*)d_in[10];
    const float* b1_buys    = (const float*)d_in[11];
    const float* W2_buys    = (const float*)d_in[12];
    const float* b2_buys    = (const float*)d_in[13];

    const int NU = 100000, NI = 200000;
    const int E  = in_sizes[2];                 // 500000
    float* out = (float*)d_out;

    float* scratch = nullptr;
    cudaGetSymbolAddress((void**)&scratch, g_scratch);
    float* Pc = scratch;
    float* Qc = Pc + P_ELEMS;
    float* Pb = Qc + Q_ELEMS;
    float* Qb = Pb + P_ELEMS;

    const int smem = (TILE_R * IN_DIM + IN_DIM * HID) * sizeof(float); // 160 KB
    cudaFuncSetAttribute(proj_kernel, cudaFuncAttributeMaxDynamicSharedMemorySize, smem);

    const int gU = (NU + TILE_R - 1) / TILE_R;   // 1563
    const int gI = (NI + TILE_R - 1) / TILE_R;   // 3125
    const size_t whalf = (size_t)IN_DIM * HID;   // offset to W1[d:]

    proj_kernel<<<gU, 256, smem>>>(user_embed, NU, W1_clicks,         Pc);
    proj_kernel<<<gI, 256, smem>>>(item_embed, NI, W1_clicks + whalf, Qc);
    proj_kernel<<<gU, 256, smem>>>(user_embed, NU, W1_buys,           Pb);
    proj_kernel<<<gI, 256, smem>>>(item_embed, NI, W1_buys + whalf,   Qb);

    const int eb = (E + 7) / 8;   // 8 warps (edges) per 256-thread block
    edge_kernel<<<eb, 256>>>(u_clicks, v_clicks, Pc, Qc, b1_clicks, W2_clicks,
                             b2_clicks, out, E);
    edge_kernel<<<eb, 256>>>(u_buys, v_buys, Pb, Qb, b1_buys, W2_buys,
                             b2_buys, out + E, E);
}

// round 2
// speedup vs baseline: 1.5284x; 1.5284x over previous
#include <cuda_runtime.h>
#include <cstdint>

#define IN_DIM 128
#define HID    256
#define TILE_R 128
#define PTHREADS 512

#define P_ELEMS (100000u * 256u)
#define Q_ELEMS (200000u * 256u)
__device__ float g_scratch[2u * (P_ELEMS + Q_ELEMS)];

// ---------------------------------------------------------------------------
// proj: P[r,:] = A[r,:128] @ W[:128,:256]
// 512 threads, 128-row x 256-col tile. Each thread: 8 rows x 4 col-pairs,
// accumulated with packed fma.rn.f32x2 (FFMA2, 2x fp32 FMA throughput).
// Columns owned by a thread: 2*lane + 64*jj2  (adjacent pair -> LDS.64).
// ---------------------------------------------------------------------------
__global__ __launch_bounds__(PTHREADS, 1)
void proj_kernel(const float4* __restrict__ A, int N,
                 const float4* __restrict__ W,   // [128,256] fp32 row-major
                 float* __restrict__ P) {
    extern __shared__ float sm[];
    float* As = sm;                       // 128*128 = 64KB
    float* Ws = sm + TILE_R * IN_DIM;     // 128*256 = 128KB

    const int tid = threadIdx.x;
    const int r0  = blockIdx.x * TILE_R;

    // Stage W: 8192 float4
    float4* Ws4 = (float4*)Ws;
    #pragma unroll
    for (int i = tid; i < IN_DIM * HID / 4; i += PTHREADS) Ws4[i] = W[i];

    // Stage A: 4096 float4 (32 float4 per row), zero-pad rows >= N
    float4* As4 = (float4*)As;
    #pragma unroll
    for (int i = tid; i < TILE_R * IN_DIM / 4; i += PTHREADS) {
        int r  = i >> 5;            // / 32
        int c  = i & 31;
        int rg = r0 + r;
        As4[i] = (rg < N) ? A[(size_t)rg * (IN_DIM / 4) + c]
                          : make_float4(0.f, 0.f, 0.f, 0.f);
    }
    __syncthreads();

    const int lane = tid & 31;
    const int warp = tid >> 5;      // 0..15

    unsigned long long acc[8][4];
    #pragma unroll
    for (int rr = 0; rr < 8; rr++)
        #pragma unroll
        for (int j = 0; j < 4; j++) acc[rr][j] = 0ull;

    const float* wbase = Ws + 2 * lane;

    #pragma unroll 4
    for (int k = 0; k < IN_DIM; k++) {
        // W column-pairs for this k: LDS.64, conflict-free (consecutive lanes)
        unsigned long long w2[4];
        #pragma unroll
        for (int j = 0; j < 4; j++)
            w2[j] = *(const unsigned long long*)(wbase + k * HID + 64 * j);

        // A values (warp-uniform broadcast LDS), packed into both f32x2 halves
        unsigned long long a2[8];
        #pragma unroll
        for (int rr = 0; rr < 8; rr++) {
            float av = As[(warp + 16 * rr) * IN_DIM + k];
            asm("mov.b64 %0, {%1, %1};" : "=l"(a2[rr]) : "f"(av));
        }

        #pragma unroll
        for (int rr = 0; rr < 8; rr++)
            #pragma unroll
            for (int j = 0; j < 4; j++)
                asm("fma.rn.f32x2 %0, %1, %2, %0;"
                    : "+l"(acc[rr][j]) : "l"(a2[rr]), "l"(w2[j]));
    }

    #pragma unroll
    for (int rr = 0; rr < 8; rr++) {
        int r = r0 + warp + 16 * rr;
        if (r < N) {
            float* dst = P + (size_t)r * HID + 2 * lane;
            #pragma unroll
            for (int j = 0; j < 4; j++)
                *(float2*)(dst + 64 * j) = *(float2*)&acc[rr][j];
        }
    }
}

// ---------------------------------------------------------------------------
// edge: one warp per edge, vectorized float4 gathers.
// logit = sum_j relu(P[u][j] + Q[v][j] + b1[j]) * W2[j] + b2
// ---------------------------------------------------------------------------
__global__ __launch_bounds__(256)
void edge_kernel(const int* __restrict__ uidx, const int* __restrict__ vidx,
                 const float4* __restrict__ P, const float4* __restrict__ Q,
                 const float4* __restrict__ b1, const float4* __restrict__ W2,
                 const float* __restrict__ b2, float* __restrict__ out, int E) {
    const int gwarp = (blockIdx.x * blockDim.x + threadIdx.x) >> 5;
    const int lane  = threadIdx.x & 31;
    if (gwarp >= E) return;

    const int u = __ldg(uidx + gwarp);
    const int v = __ldg(vidx + gwarp);
    const float4* pu = P + (size_t)u * (HID / 4);
    const float4* qv = Q + (size_t)v * (HID / 4);

    float acc = 0.0f;
    #pragma unroll
    for (int s = 0; s < 2; s++) {
        int j = lane + 32 * s;
        float4 p = pu[j];
        float4 q = qv[j];
        float4 b = __ldg(b1 + j);
        float4 w = __ldg(W2 + j);
        float h0 = fmaxf(p.x + q.x + b.x, 0.f);
        float h1 = fmaxf(p.y + q.y + b.y, 0.f);
        float h2 = fmaxf(p.z + q.z + b.z, 0.f);
        float h3 = fmaxf(p.w + q.w + b.w, 0.f);
        acc = fmaf(h0, w.x, acc);
        acc = fmaf(h1, w.y, acc);
        acc = fmaf(h2, w.z, acc);
        acc = fmaf(h3, w.w, acc);
    }
    #pragma unroll
    for (int o = 16; o; o >>= 1) acc += __shfl_xor_sync(0xffffffffu, acc, o);

    if (lane == 0) out[gwarp] = acc + __ldg(b2);
}

// ---------------------------------------------------------------------------
extern "C" void kernel_launch(void* const* d_in, const int* in_sizes, int n_in,
                              void* d_out, int out_size) {
    const float* user_embed = (const float*)d_in[0];
    const float* item_embed = (const float*)d_in[1];
    const int*   u_clicks   = (const int*)  d_in[2];
    const int*   v_clicks   = (const int*)  d_in[3];
    const int*   u_buys     = (const int*)  d_in[4];
    const int*   v_buys     = (const int*)  d_in[5];
    const float* W1_clicks  = (const float*)d_in[6];
    const float* b1_clicks  = (const float*)d_in[7];
    const float* W2_clicks  = (const float*)d_in[8];
    const float* b2_clicks  = (const float*)d_in[9];
    const float* W1_buys    = (const float*)d_in[10];
    const float* b1_buys    = (const float*)d_in[11];
    const float* W2_buys    = (const float*)d_in[12];
    const float* b2_buys    = (const float*)d_in[13];

    const int NU = 100000, NI = 200000;
    const int E  = in_sizes[2];
    float* out = (float*)d_out;

    float* scratch = nullptr;
    cudaGetSymbolAddress((void**)&scratch, g_scratch);
    float* Pc = scratch;
    float* Qc = Pc + P_ELEMS;
    float* Pb = Qc + Q_ELEMS;
    float* Qb = Pb + P_ELEMS;

    const int smem = (TILE_R * IN_DIM + IN_DIM * HID) * sizeof(float); // 192KB
    static bool attr_set = false;
    if (!attr_set) {
        cudaFuncSetAttribute(proj_kernel,
                             cudaFuncAttributeMaxDynamicSharedMemorySize, smem);
        attr_set = true;
    }

    const int gU = (NU + TILE_R - 1) / TILE_R;   // 782
    const int gI = (NI + TILE_R - 1) / TILE_R;   // 1563
    const size_t whalf = (size_t)IN_DIM * HID;

    proj_kernel<<<gU, PTHREADS, smem>>>((const float4*)user_embed, NU,
                                        (const float4*)W1_clicks, Pc);
    proj_kernel<<<gI, PTHREADS, smem>>>((const float4*)item_embed, NI,
                                        (const float4*)(W1_clicks + whalf), Qc);
    proj_kernel<<<gU, PTHREADS, smem>>>((const float4*)user_embed, NU,
                                        (const float4*)W1_buys, Pb);
    proj_kernel<<<gI, PTHREADS, smem>>>((const float4*)item_embed, NI,
                                        (const float4*)(W1_buys + whalf), Qb);

    const int eb = (E + 7) / 8;
    edge_kernel<<<eb, 256>>>(u_clicks, v_clicks, (const float4*)Pc,
                             (const float4*)Qc, (const float4*)b1_clicks,
                             (const float4*)W2_clicks, b2_clicks, out, E);
    edge_kernel<<<eb, 256>>>(u_buys, v_buys, (const float4*)Pb,
                             (const float4*)Qb, (const float4*)b1_buys,
                             (const float4*)W2_buys, b2_buys, out + E, E);
}

// round 4
// speedup vs baseline: 2.6649x; 1.7436x over previous
#include <cuda_runtime.h>
#include <cuda_bf16.h>
#include <cstdint>

#define IN_DIM 128
#define HID    256
#define NU 100000
#define NI 200000
#define NTILE_U ((NU + 127) / 128)   // 782
#define NTILE_I ((NI + 127) / 128)   // 1563
#define KEXT 384                     // [Ah | Ah | Al] x [Wh ; Wl ; Wh]

#define P_ELEMS (100000u * 256u)
#define Q_ELEMS (200000u * 256u)
__device__ float g_scratch[2u * (P_ELEMS + Q_ELEMS)];

// bf16 extended operands
__device__ __align__(16) __nv_bfloat16 g_aext_u[(size_t)NTILE_U * 128 * KEXT];
__device__ __align__(16) __nv_bfloat16 g_aext_i[(size_t)NTILE_I * 128 * KEXT];
__device__ __align__(16) __nv_bfloat16 g_wext[4][HID * KEXT];   // [n][k] row-major

// ---------------------------------------------------------------------------
__device__ __forceinline__ uint32_t smem_u32(const void* p) {
    uint32_t a;
    asm("{ .reg .u64 t; cvta.to.shared.u64 t, %1; cvt.u32.u64 %0, t; }"
        : "=r"(a) : "l"(p));
    return a;
}
__device__ __forceinline__ uint32_t swz(uint32_t o) { return o ^ ((o >> 3) & 0x70); }
__device__ __forceinline__ uint32_t pack2(float a, float b) {
    __nv_bfloat162 t = __floats2bfloat162_rn(a, b);
    return *(uint32_t*)&t;
}

// ---------------------------------------------------------------------------
// convA: fp32 A[N,128] -> Aext[tiles*128, 384] bf16 row-major = [Ah | Ah | Al]
// ---------------------------------------------------------------------------
__global__ __launch_bounds__(256)
void convA_kernel(const float* __restrict__ A, int N, __nv_bfloat16* __restrict__ Aext) {
    const int t0 = blockIdx.x;
    for (int idx = threadIdx.x; idx < 128 * 32; idx += 256) {
        const int r = idx >> 5, c4 = idx & 31;       // row in tile, float4 col
        const int rg = t0 * 128 + r;
        float4 v = make_float4(0.f, 0.f, 0.f, 0.f);
        if (rg < N) v = *(const float4*)(A + (size_t)rg * IN_DIM + c4 * 4);
        float h0 = __bfloat162float(__float2bfloat16_rn(v.x));
        float h1 = __bfloat162float(__float2bfloat16_rn(v.y));
        float h2 = __bfloat162float(__float2bfloat16_rn(v.z));
        float h3 = __bfloat162float(__float2bfloat16_rn(v.w));
        uint2 uh = { pack2(h0, h1), pack2(h2, h3) };
        uint2 ul = { pack2(v.x - h0, v.y - h1), pack2(v.z - h2, v.w - h3) };
        __nv_bfloat16* row = Aext + (size_t)(t0 * 128 + r) * KEXT + c4 * 4;
        *(uint2*)(row)       = uh;   // Ah
        *(uint2*)(row + 128) = uh;   // Ah
        *(uint2*)(row + 256) = ul;   // Al
    }
}

// ---------------------------------------------------------------------------
// convW: fp32 W-half [128 k][256 n] -> Wext [256 n][384 k] = [Wh ; Wl ; Wh]
// ---------------------------------------------------------------------------
__global__ __launch_bounds__(256)
void convW_kernel(const float* __restrict__ Wsrc, __nv_bfloat16* __restrict__ Wext) {
    for (int idx = blockIdx.x * 256 + threadIdx.x; idx < HID * IN_DIM;
         idx += gridDim.x * 256) {
        const int n = idx >> 7, k = idx & 127;
        const float x = Wsrc[(size_t)k * HID + n];
        const __nv_bfloat16 h = __float2bfloat16_rn(x);
        const float l = x - __bfloat162float(h);
        __nv_bfloat16* row = Wext + (size_t)n * KEXT;
        row[k]       = h;
        row[128 + k] = __float2bfloat16_rn(l);
        row[256 + k] = h;
    }
}

// ---------------------------------------------------------------------------
// gemm: P[rt*128 .. , ch*128 ..] = Aext[128,384] @ Wext[384,128(half)]^T
// 256 thr = 8 warps (4 m x 2 n), warp tile 32x64, mma.sync m16n8k16 bf16.
// cp.async double-buffered K-chunks of 64 (A 16KB + B 16KB per chunk).
// ---------------------------------------------------------------------------
#define KC 64
#define NCHUNK 6
#define BUF_BYTES 32768

__device__ __forceinline__ void ldsm4(uint32_t* r, uint32_t a) {
    asm volatile("ldmatrix.sync.aligned.m8n8.x4.shared.b16 {%0,%1,%2,%3}, [%4];"
                 : "=r"(r[0]), "=r"(r[1]), "=r"(r[2]), "=r"(r[3]) : "r"(a));
}
__device__ __forceinline__ void mma16816(float* d, const uint32_t* a, const uint32_t* b) {
    asm volatile("mma.sync.aligned.m16n8k16.row.col.f32.bf16.bf16.f32 "
                 "{%0,%1,%2,%3}, {%4,%5,%6,%7}, {%8,%9}, {%0,%1,%2,%3};"
                 : "+f"(d[0]), "+f"(d[1]), "+f"(d[2]), "+f"(d[3])
                 : "r"(a[0]), "r"(a[1]), "r"(a[2]), "r"(a[3]), "r"(b[0]), "r"(b[1]));
}

__global__ __launch_bounds__(256, 2)
void gemm_kernel(const __nv_bfloat16* __restrict__ Aext, int N,
                 const __nv_bfloat16* __restrict__ Wext,
                 float* __restrict__ P) {
    extern __shared__ __align__(1024) unsigned char sm[];
    const uint32_t sbase = smem_u32(sm);
    const int tid  = threadIdx.x;
    const int lane = tid & 31;
    const int wid  = tid >> 5;
    const int wm   = wid & 3;        // 0..3 (m)
    const int wn   = wid >> 2;       // 0..1 (n)
    const int row0 = blockIdx.x * 128;
    const int ch   = blockIdx.y;     // col half

    const char* Abase = (const char*)(Aext + (size_t)row0 * KEXT);
    const char* Bbase = (const char*)(Wext + (size_t)(ch * 128) * KEXT);

    // cp.async one chunk (c = 0..5): A rows 0..127 k-slice, B n-rows 0..127
    auto issue = [&](int c) {
        const uint32_t sa = sbase + (uint32_t)(c & 1) * BUF_BYTES;
        const uint32_t sb = sa + 16384;
        #pragma unroll
        for (int i = 0; i < 4; i++) {
            const int idx = tid + i * 256;
            const int r = idx >> 3, c16 = idx & 7;
            const size_t go = (size_t)r * (KEXT * 2) + c * (KC * 2) + c16 * 16;
            const uint32_t so = swz((uint32_t)(r * 128 + c16 * 16));
            asm volatile("cp.async.cg.shared.global [%0], [%1], 16;"
                         :: "r"(sa + so), "l"(Abase + go) : "memory");
            asm volatile("cp.async.cg.shared.global [%0], [%1], 16;"
                         :: "r"(sb + so), "l"(Bbase + go) : "memory");
        }
        asm volatile("cp.async.commit_group;" ::: "memory");
    };

    float acc[2][8][4];
    #pragma unroll
    for (int mt = 0; mt < 2; mt++)
        #pragma unroll
        for (int nt = 0; nt < 8; nt++)
            #pragma unroll
            for (int j = 0; j < 4; j++) acc[mt][nt][j] = 0.f;

    issue(0);
    #pragma unroll
    for (int c = 0; c < NCHUNK; c++) {
        if (c + 1 < NCHUNK) {
            issue(c + 1);
            asm volatile("cp.async.wait_group 1;" ::: "memory");
        } else {
            asm volatile("cp.async.wait_group 0;" ::: "memory");
        }
        __syncthreads();

        const uint32_t sa = sbase + (uint32_t)(c & 1) * BUF_BYTES;
        const uint32_t sb = sa + 16384;
        #pragma unroll
        for (int ks = 0; ks < KC / 16; ks++) {
            uint32_t af[2][4];
            #pragma unroll
            for (int mt = 0; mt < 2; mt++) {
                const int row = wm * 32 + mt * 16 + (lane & 15);
                const uint32_t off = (uint32_t)(row * 128 + ks * 32 + (lane >> 4) * 16);
                ldsm4(af[mt], sa + swz(off));
            }
            uint32_t bf[8][2];
            #pragma unroll
            for (int ntp = 0; ntp < 4; ntp++) {
                const int nrow = wn * 64 + ntp * 16 + ((lane >> 4) << 3) + (lane & 7);
                const uint32_t off = (uint32_t)(nrow * 128 + ks * 32 + ((lane >> 3) & 1) * 16);
                uint32_t r4[4];
                ldsm4(r4, sb + swz(off));
                bf[2 * ntp][0] = r4[0]; bf[2 * ntp][1] = r4[1];
                bf[2 * ntp + 1][0] = r4[2]; bf[2 * ntp + 1][1] = r4[3];
            }
            #pragma unroll
            for (int mt = 0; mt < 2; mt++)
                #pragma unroll
                for (int nt = 0; nt < 8; nt++)
                    mma16816(acc[mt][nt], af[mt], bf[nt]);
        }
        __syncthreads();
    }

    // Epilogue: c0,c1 -> (row, col..col+1); c2,c3 -> (row+8, ...)
    const int rb = row0 + wm * 32 + (lane >> 2);
    const int cb = ch * 128 + wn * 64 + (lane & 3) * 2;
    #pragma unroll
    for (int mt = 0; mt < 2; mt++) {
        #pragma unroll
        for (int half = 0; half < 2; half++) {
            const int r = rb + mt * 16 + half * 8;
            if (r < N) {
                float* dst = P + (size_t)r * HID + cb;
                #pragma unroll
                for (int nt = 0; nt < 8; nt++) {
                    float2 v = { acc[mt][nt][half * 2], acc[mt][nt][half * 2 + 1] };
                    *(float2*)(dst + nt * 8) = v;
                }
            }
        }
    }
}

// ---------------------------------------------------------------------------
// edge: one warp per edge (DRAM-bound gather)
// ---------------------------------------------------------------------------
__global__ __launch_bounds__(256)
void edge_kernel(const int* __restrict__ uidx, const int* __restrict__ vidx,
                 const float4* __restrict__ P, const float4* __restrict__ Q,
                 const float4* __restrict__ b1, const float4* __restrict__ W2,
                 const float* __restrict__ b2, float* __restrict__ out, int E) {
    const int gwarp = (blockIdx.x * blockDim.x + threadIdx.x) >> 5;
    const int lane  = threadIdx.x & 31;
    if (gwarp >= E) return;
    const int u = __ldg(uidx + gwarp);
    const int v = __ldg(vidx + gwarp);
    const float4* pu = P + (size_t)u * (HID / 4);
    const float4* qv = Q + (size_t)v * (HID / 4);
    float acc = 0.0f;
    #pragma unroll
    for (int s = 0; s < 2; s++) {
        int j = lane + 32 * s;
        float4 p = pu[j], q = qv[j];
        float4 b = __ldg(b1 + j), w = __ldg(W2 + j);
        acc = fmaf(fmaxf(p.x + q.x + b.x, 0.f), w.x, acc);
        acc = fmaf(fmaxf(p.y + q.y + b.y, 0.f), w.y, acc);
        acc = fmaf(fmaxf(p.z + q.z + b.z, 0.f), w.z, acc);
        acc = fmaf(fmaxf(p.w + q.w + b.w, 0.f), w.w, acc);
    }
    #pragma unroll
    for (int o = 16; o; o >>= 1) acc += __shfl_xor_sync(0xffffffffu, acc, o);
    if (lane == 0) out[gwarp] = acc + __ldg(b2);
}

// ---------------------------------------------------------------------------
extern "C" void kernel_launch(void* const* d_in, const int* in_sizes, int n_in,
                              void* d_out, int out_size) {
    const float* user_embed = (const float*)d_in[0];
    const float* item_embed = (const float*)d_in[1];
    const int*   u_clicks   = (const int*)  d_in[2];
    const int*   v_clicks   = (const int*)  d_in[3];
    const int*   u_buys     = (const int*)  d_in[4];
    const int*   v_buys     = (const int*)  d_in[5];
    const float* W1_clicks  = (const float*)d_in[6];
    const float* b1_clicks  = (const float*)d_in[7];
    const float* W2_clicks  = (const float*)d_in[8];
    const float* b2_clicks  = (const float*)d_in[9];
    const float* W1_buys    = (const float*)d_in[10];
    const float* b1_buys    = (const float*)d_in[11];
    const float* W2_buys    = (const float*)d_in[12];
    const float* b2_buys    = (const float*)d_in[13];

    const int E = in_sizes[2];
    float* out = (float*)d_out;

    float* scratch = nullptr;
    cudaGetSymbolAddress((void**)&scratch, g_scratch);
    float* Pc = scratch;
    float* Qc = Pc + P_ELEMS;
    float* Pb = Qc + Q_ELEMS;
    float* Qb = Pb + P_ELEMS;

    __nv_bfloat16 *aext_u = nullptr, *aext_i = nullptr, *wext = nullptr;
    cudaGetSymbolAddress((void**)&aext_u, g_aext_u);
    cudaGetSymbolAddress((void**)&aext_i, g_aext_i);
    cudaGetSymbolAddress((void**)&wext,   g_wext);

    static bool attr_set = false;
    if (!attr_set) {
        cudaFuncSetAttribute(gemm_kernel,
                             cudaFuncAttributeMaxDynamicSharedMemorySize,
                             2 * BUF_BYTES);
        attr_set = true;
    }

    const size_t whalf = (size_t)IN_DIM * HID;
    const size_t wstride = (size_t)HID * KEXT;
    convW_kernel<<<16, 256>>>(W1_clicks,         wext + 0 * wstride);
    convW_kernel<<<16, 256>>>(W1_clicks + whalf, wext + 1 * wstride);
    convW_kernel<<<16, 256>>>(W1_buys,           wext + 2 * wstride);
    convW_kernel<<<16, 256>>>(W1_buys + whalf,   wext + 3 * wstride);

    convA_kernel<<<NTILE_U, 256>>>(user_embed, NU, aext_u);
    convA_kernel<<<NTILE_I, 256>>>(item_embed, NI, aext_i);

    gemm_kernel<<<dim3(NTILE_U, 2), 256, 2 * BUF_BYTES>>>(aext_u, NU, wext + 0 * wstride, Pc);
    gemm_kernel<<<dim3(NTILE_I, 2), 256, 2 * BUF_BYTES>>>(aext_i, NI, wext + 1 * wstride, Qc);
    gemm_kernel<<<dim3(NTILE_U, 2), 256, 2 * BUF_BYTES>>>(aext_u, NU, wext + 2 * wstride, Pb);
    gemm_kernel<<<dim3(NTILE_I, 2), 256, 2 * BUF_BYTES>>>(aext_i, NI, wext + 3 * wstride, Qb);

    const int eb = (E + 7) / 8;
    edge_kernel<<<eb, 256>>>(u_clicks, v_clicks, (const float4*)Pc,
                             (const float4*)Qc, (const float4*)b1_clicks,
                             (const float4*)W2_clicks, b2_clicks, out, E);
    edge_kernel<<<eb, 256>>>(u_buys, v_buys, (const float4*)Pb,
                             (const float4*)Qb, (const float4*)b1_buys,
                             (const float4*)W2_buys, b2_buys, out + E, E);
}

// round 5
// speedup vs baseline: 2.7072x; 1.0159x over previous
#include <cuda_runtime.h>
#include <cuda_bf16.h>
#include <cstdint>

#define IN_DIM 128
#define HID    256
#define NU 100000
#define NI 200000
#define NTILE_U ((NU + 127) / 128)   // 782
#define NTILE_I ((NI + 127) / 128)   // 1563
#define KA   256                     // A: [Ah | Al]
#define KEXT 384                     // B: [Wh ; Wl ; Wh]

#define P_ELEMS (100000u * 256u)
#define Q_ELEMS (200000u * 256u)
__device__ float g_scratch[2u * (P_ELEMS + Q_ELEMS)];

__device__ __align__(16) __nv_bfloat16 g_aext_u[(size_t)NTILE_U * 128 * KA];
__device__ __align__(16) __nv_bfloat16 g_aext_i[(size_t)NTILE_I * 128 * KA];
__device__ __align__(16) __nv_bfloat16 g_wext[4][HID * KEXT];   // [n][kext]

// ---------------------------------------------------------------------------
__device__ __forceinline__ uint32_t smem_u32(const void* p) {
    uint32_t a;
    asm("{ .reg .u64 t; cvta.to.shared.u64 t, %1; cvt.u32.u64 %0, t; }"
        : "=r"(a) : "l"(p));
    return a;
}
__device__ __forceinline__ uint32_t swz(uint32_t o) { return o ^ ((o >> 3) & 0x70); }
__device__ __forceinline__ uint32_t pack2(float a, float b) {
    __nv_bfloat162 t = __floats2bfloat162_rn(a, b);
    return *(uint32_t*)&t;
}

// ---------------------------------------------------------------------------
// convA: fp32 A[N,128] -> Aext[tiles*128, 256] bf16 row-major = [Ah | Al]
// ---------------------------------------------------------------------------
__global__ __launch_bounds__(256)
void convA_kernel(const float* __restrict__ A, int N, __nv_bfloat16* __restrict__ Aext) {
    const int t0 = blockIdx.x;
    for (int idx = threadIdx.x; idx < 128 * 32; idx += 256) {
        const int r = idx >> 5, c4 = idx & 31;
        const int rg = t0 * 128 + r;
        float4 v = make_float4(0.f, 0.f, 0.f, 0.f);
        if (rg < N) v = *(const float4*)(A + (size_t)rg * IN_DIM + c4 * 4);
        float h0 = __bfloat162float(__float2bfloat16_rn(v.x));
        float h1 = __bfloat162float(__float2bfloat16_rn(v.y));
        float h2 = __bfloat162float(__float2bfloat16_rn(v.z));
        float h3 = __bfloat162float(__float2bfloat16_rn(v.w));
        uint2 uh = { pack2(h0, h1), pack2(h2, h3) };
        uint2 ul = { pack2(v.x - h0, v.y - h1), pack2(v.z - h2, v.w - h3) };
        __nv_bfloat16* row = Aext + (size_t)(t0 * 128 + r) * KA + c4 * 4;
        *(uint2*)(row)       = uh;   // Ah
        *(uint2*)(row + 128) = ul;   // Al
    }
}

// ---------------------------------------------------------------------------
// convW: fp32 W-half [128 k][256 n] -> Wext [256 n][384] = [Wh | Wl | Wh]
// ---------------------------------------------------------------------------
__global__ __launch_bounds__(256)
void convW_kernel(const float* __restrict__ Wsrc, __nv_bfloat16* __restrict__ Wext) {
    for (int idx = blockIdx.x * 256 + threadIdx.x; idx < HID * IN_DIM;
         idx += gridDim.x * 256) {
        const int n = idx >> 7, k = idx & 127;
        const float x = Wsrc[(size_t)k * HID + n];
        const __nv_bfloat16 h = __float2bfloat16_rn(x);
        const float l = x - __bfloat162float(h);
        __nv_bfloat16* row = Wext + (size_t)n * KEXT;
        row[k]       = h;
        row[128 + k] = __float2bfloat16_rn(l);
        row[256 + k] = h;
    }
}

// ---------------------------------------------------------------------------
// fused gemm: per CTA (one 128-row tile): load A once (64KB smem),
// loop over 2 tasks x 6 B-chunks (B double-buffered 2x32KB).
// A smem chunk map per B chunk: {Ah0,Ah1, Ah0,Ah1, Al0,Al1}.
// 512 thr = 16 warps (4m x 4n), warp tile 32x64, mma m16n8k16 bf16.
// ---------------------------------------------------------------------------
#define KC 64
#define SM_B_OFF 65536
#define GEMM_SMEM (65536 + 2 * 32768)

__device__ __forceinline__ void ldsm4(uint32_t* r, uint32_t a) {
    asm volatile("ldmatrix.sync.aligned.m8n8.x4.shared.b16 {%0,%1,%2,%3}, [%4];"
                 : "=r"(r[0]), "=r"(r[1]), "=r"(r[2]), "=r"(r[3]) : "r"(a));
}
__device__ __forceinline__ void mma16816(float* d, const uint32_t* a, const uint32_t* b) {
    asm volatile("mma.sync.aligned.m16n8k16.row.col.f32.bf16.bf16.f32 "
                 "{%0,%1,%2,%3}, {%4,%5,%6,%7}, {%8,%9}, {%0,%1,%2,%3};"
                 : "+f"(d[0]), "+f"(d[1]), "+f"(d[2]), "+f"(d[3])
                 : "r"(a[0]), "r"(a[1]), "r"(a[2]), "r"(a[3]), "r"(b[0]), "r"(b[1]));
}

__global__ __launch_bounds__(512, 1)
void gemm_kernel(const __nv_bfloat16* __restrict__ Aext, int N,
                 const __nv_bfloat16* __restrict__ W0,
                 const __nv_bfloat16* __restrict__ W1,
                 float* __restrict__ P0, float* __restrict__ P1) {
    extern __shared__ __align__(1024) unsigned char sm[];
    const uint32_t sbase = smem_u32(sm);
    const int tid  = threadIdx.x;
    const int lane = tid & 31;
    const int wid  = tid >> 5;
    const int wm   = wid & 3;        // 0..3
    const int wn   = wid >> 2;       // 0..3
    const int row0 = blockIdx.x * 128;

    const char* Abase = (const char*)(Aext + (size_t)row0 * KA);

    // B chunk issue: it in 0..11, task = it/6, c = it%6
    auto issue_b = [&](int it) {
        const char* Bb = (const char*)((it < 6) ? W0 : W1);
        const int c = (it < 6) ? it : it - 6;
        const uint32_t sb = sbase + SM_B_OFF + (uint32_t)(it & 1) * 32768;
        #pragma unroll
        for (int i = 0; i < 4; i++) {
            const int idx = tid + i * 512;
            const int r = idx >> 3, s = idx & 7;           // n-row, 16B sector
            const size_t go = (size_t)r * (KEXT * 2) + c * (KC * 2) + s * 16;
            const uint32_t so = swz((uint32_t)(r * 128 + s * 16));
            asm volatile("cp.async.cg.shared.global [%0], [%1], 16;"
                         :: "r"(sb + so), "l"(Bb + go) : "memory");
        }
        asm volatile("cp.async.commit_group;" ::: "memory");
    };

    // A tile: 4 chunks of [128 rows x 64 k] (16KB each), loaded once
    {
        #pragma unroll
        for (int i = 0; i < 8; i++) {
            const int idx = tid + i * 512;
            const int r = idx >> 5, ck = (idx >> 3) & 3, s = idx & 7;
            const size_t go = (size_t)r * (KA * 2) + ck * (KC * 2) + s * 16;
            const uint32_t so = (uint32_t)(ck * 16384) + swz((uint32_t)(r * 128 + s * 16));
            asm volatile("cp.async.cg.shared.global [%0], [%1], 16;"
                         :: "r"(sbase + so), "l"(Abase + go) : "memory");
        }
    }
    issue_b(0);   // commit group 0 = A tile + B chunk 0

    float acc[2][8][4];
    #pragma unroll
    for (int mt = 0; mt < 2; mt++)
        #pragma unroll
        for (int nt = 0; nt < 8; nt++)
            #pragma unroll
            for (int j = 0; j < 4; j++) acc[mt][nt][j] = 0.f;

    const int amap[6] = {0, 1, 0, 1, 2, 3};

    #pragma unroll
    for (int it = 0; it < 12; it++) {
        if (it + 1 < 12) {
            issue_b(it + 1);
            asm volatile("cp.async.wait_group 1;" ::: "memory");
        } else {
            asm volatile("cp.async.wait_group 0;" ::: "memory");
        }
        __syncthreads();

        const uint32_t sa = sbase + (uint32_t)(amap[it % 6] * 16384);
        const uint32_t sb = sbase + SM_B_OFF + (uint32_t)(it & 1) * 32768;

        #pragma unroll
        for (int ks = 0; ks < KC / 16; ks++) {
            uint32_t af[2][4];
            #pragma unroll
            for (int mt = 0; mt < 2; mt++) {
                const int row = wm * 32 + mt * 16 + (lane & 15);
                const uint32_t off = (uint32_t)(row * 128 + ks * 32 + (lane >> 4) * 16);
                ldsm4(af[mt], sa + swz(off));
            }
            uint32_t bfr[8][2];
            #pragma unroll
            for (int ntp = 0; ntp < 4; ntp++) {
                const int nrow = wn * 64 + ntp * 16 + ((lane >> 4) << 3) + (lane & 7);
                const uint32_t off = (uint32_t)(nrow * 128 + ks * 32 + ((lane >> 3) & 1) * 16);
                uint32_t r4[4];
                ldsm4(r4, sb + swz(off));
                bfr[2 * ntp][0] = r4[0]; bfr[2 * ntp][1] = r4[1];
                bfr[2 * ntp + 1][0] = r4[2]; bfr[2 * ntp + 1][1] = r4[3];
            }
            #pragma unroll
            for (int mt = 0; mt < 2; mt++)
                #pragma unroll
                for (int nt = 0; nt < 8; nt++)
                    mma16816(acc[mt][nt], af[mt], bfr[nt]);
        }
        __syncthreads();

        // End of a task's K loop: write epilogue, reset accumulators
        if (it == 5 || it == 11) {
            float* Pt = (it == 5) ? P0 : P1;
            const int rb = row0 + wm * 32 + (lane >> 2);
            const int cb = wn * 64 + (lane & 3) * 2;
            #pragma unroll
            for (int mt = 0; mt < 2; mt++) {
                #pragma unroll
                for (int half = 0; half < 2; half++) {
                    const int r = rb + mt * 16 + half * 8;
                    if (r < N) {
                        float* dst = Pt + (size_t)r * HID + cb;
                        #pragma unroll
                        for (int nt = 0; nt < 8; nt++) {
                            float2 v = { acc[mt][nt][half * 2], acc[mt][nt][half * 2 + 1] };
                            *(float2*)(dst + nt * 8) = v;
                        }
                    }
                }
            }
            #pragma unroll
            for (int mt = 0; mt < 2; mt++)
                #pragma unroll
                for (int nt = 0; nt < 8; nt++)
                    #pragma unroll
                    for (int j = 0; j < 4; j++) acc[mt][nt][j] = 0.f;
        }
    }
}

// ---------------------------------------------------------------------------
// edge: one warp per edge (DRAM-bound gather)
// ---------------------------------------------------------------------------
__global__ __launch_bounds__(256)
void edge_kernel(const int* __restrict__ uidx, const int* __restrict__ vidx,
                 const float4* __restrict__ P, const float4* __restrict__ Q,
                 const float4* __restrict__ b1, const float4* __restrict__ W2,
                 const float* __restrict__ b2, float* __restrict__ out, int E) {
    const int gwarp = (blockIdx.x * blockDim.x + threadIdx.x) >> 5;
    const int lane  = threadIdx.x & 31;
    if (gwarp >= E) return;
    const int u = __ldg(uidx + gwarp);
    const int v = __ldg(vidx + gwarp);
    const float4* pu = P + (size_t)u * (HID / 4);
    const float4* qv = Q + (size_t)v * (HID / 4);
    float acc = 0.0f;
    #pragma unroll
    for (int s = 0; s < 2; s++) {
        int j = lane + 32 * s;
        float4 p = pu[j], q = qv[j];
        float4 b = __ldg(b1 + j), w = __ldg(W2 + j);
        acc = fmaf(fmaxf(p.x + q.x + b.x, 0.f), w.x, acc);
        acc = fmaf(fmaxf(p.y + q.y + b.y, 0.f), w.y, acc);
        acc = fmaf(fmaxf(p.z + q.z + b.z, 0.f), w.z, acc);
        acc = fmaf(fmaxf(p.w + q.w + b.w, 0.f), w.w, acc);
    }
    #pragma unroll
    for (int o = 16; o; o >>= 1) acc += __shfl_xor_sync(0xffffffffu, acc, o);
    if (lane == 0) out[gwarp] = acc + __ldg(b2);
}

// ---------------------------------------------------------------------------
extern "C" void kernel_launch(void* const* d_in, const int* in_sizes, int n_in,
                              void* d_out, int out_size) {
    const float* user_embed = (const float*)d_in[0];
    const float* item_embed = (const float*)d_in[1];
    const int*   u_clicks   = (const int*)  d_in[2];
    const int*   v_clicks   = (const int*)  d_in[3];
    const int*   u_buys     = (const int*)  d_in[4];
    const int*   v_buys     = (const int*)  d_in[5];
    const float* W1_clicks  = (const float*)d_in[6];
    const float* b1_clicks  = (const float*)d_in[7];
    const float* W2_clicks  = (const float*)d_in[8];
    const float* b2_clicks  = (const float*)d_in[9];
    const float* W1_buys    = (const float*)d_in[10];
    const float* b1_buys    = (const float*)d_in[11];
    const float* W2_buys    = (const float*)d_in[12];
    const float* b2_buys    = (const float*)d_in[13];

    const int E = in_sizes[2];
    float* out = (float*)d_out;

    float* scratch = nullptr;
    cudaGetSymbolAddress((void**)&scratch, g_scratch);
    float* Pc = scratch;
    float* Qc = Pc + P_ELEMS;
    float* Pb = Qc + Q_ELEMS;
    float* Qb = Pb + P_ELEMS;

    __nv_bfloat16 *aext_u = nullptr, *aext_i = nullptr, *wext = nullptr;
    cudaGetSymbolAddress((void**)&aext_u, g_aext_u);
    cudaGetSymbolAddress((void**)&aext_i, g_aext_i);
    cudaGetSymbolAddress((void**)&wext,   g_wext);

    static bool attr_set = false;
    if (!attr_set) {
        cudaFuncSetAttribute(gemm_kernel,
                             cudaFuncAttributeMaxDynamicSharedMemorySize, GEMM_SMEM);
        attr_set = true;
    }

    const size_t whalf = (size_t)IN_DIM * HID;
    const size_t wstride = (size_t)HID * KEXT;
    convW_kernel<<<16, 256>>>(W1_clicks,         wext + 0 * wstride);
    convW_kernel<<<16, 256>>>(W1_clicks + whalf, wext + 1 * wstride);
    convW_kernel<<<16, 256>>>(W1_buys,           wext + 2 * wstride);
    convW_kernel<<<16, 256>>>(W1_buys + whalf,   wext + 3 * wstride);

    convA_kernel<<<NTILE_U, 256>>>(user_embed, NU, aext_u);
    convA_kernel<<<NTILE_I, 256>>>(item_embed, NI, aext_i);

    // One launch per embedding table; computes BOTH tasks' projections.
    gemm_kernel<<<NTILE_U, 512, GEMM_SMEM>>>(aext_u, NU,
                                             wext + 0 * wstride, wext + 2 * wstride,
                                             Pc, Pb);
    gemm_kernel<<<NTILE_I, 512, GEMM_SMEM>>>(aext_i, NI,
                                             wext + 1 * wstride, wext + 3 * wstride,
                                             Qc, Qb);

    const int eb = (E + 7) / 8;
    edge_kernel<<<eb, 256>>>(u_clicks, v_clicks, (const float4*)Pc,
                             (const float4*)Qc, (const float4*)b1_clicks,
                             (const float4*)W2_clicks, b2_clicks, out, E);
    edge_kernel<<<eb, 256>>>(u_buys, v_buys, (const float4*)Pb,
                             (const float4*)Qb, (const float4*)b1_buys,
                             (const float4*)W2_buys, b2_buys, out + E, E);
}

// round 6
// speedup vs baseline: 2.7234x; 1.0060x over previous
#include <cuda_runtime.h>
#include <cuda_bf16.h>
#include <cstdint>

#define IN_DIM 128
#define HID    256
#define NU 100000
#define NI 200000
#define NTILE_U ((NU + 127) / 128)   // 782
#define NTILE_I ((NI + 127) / 128)   // 1563
#define KA   256                     // A: [Ah | Al]
#define KEXT 384                     // B: [Wh ; Wl ; Wh]

#define P_ELEMS (100000u * 256u)
#define Q_ELEMS (200000u * 256u)
__device__ float g_scratch[2u * (P_ELEMS + Q_ELEMS)];

__device__ __align__(16) __nv_bfloat16 g_aext_u[(size_t)NTILE_U * 128 * KA];
__device__ __align__(16) __nv_bfloat16 g_aext_i[(size_t)NTILE_I * 128 * KA];
__device__ __align__(16) __nv_bfloat16 g_wext[4][HID * KEXT];   // [n][kext]

// ---------------------------------------------------------------------------
__device__ __forceinline__ uint32_t smem_u32(const void* p) {
    uint32_t a;
    asm("{ .reg .u64 t; cvta.to.shared.u64 t, %1; cvt.u32.u64 %0, t; }"
        : "=r"(a) : "l"(p));
    return a;
}
__device__ __forceinline__ uint32_t swz(uint32_t o) { return o ^ ((o >> 3) & 0x70); }
__device__ __forceinline__ uint32_t pack2(float a, float b) {
    __nv_bfloat162 t = __floats2bfloat162_rn(a, b);
    return *(uint32_t*)&t;
}
template <int N>
__device__ __forceinline__ void cpwait() {
    asm volatile("cp.async.wait_group %0;" :: "n"(N) : "memory");
}

// ---------------------------------------------------------------------------
// convA: fp32 A[N,128] -> Aext[tiles*128, 256] bf16 row-major = [Ah | Al]
// ---------------------------------------------------------------------------
__global__ __launch_bounds__(256)
void convA_kernel(const float* __restrict__ A, int N, __nv_bfloat16* __restrict__ Aext) {
    const int t0 = blockIdx.x;
    for (int idx = threadIdx.x; idx < 128 * 32; idx += 256) {
        const int r = idx >> 5, c4 = idx & 31;
        const int rg = t0 * 128 + r;
        float4 v = make_float4(0.f, 0.f, 0.f, 0.f);
        if (rg < N) v = *(const float4*)(A + (size_t)rg * IN_DIM + c4 * 4);
        float h0 = __bfloat162float(__float2bfloat16_rn(v.x));
        float h1 = __bfloat162float(__float2bfloat16_rn(v.y));
        float h2 = __bfloat162float(__float2bfloat16_rn(v.z));
        float h3 = __bfloat162float(__float2bfloat16_rn(v.w));
        uint2 uh = { pack2(h0, h1), pack2(h2, h3) };
        uint2 ul = { pack2(v.x - h0, v.y - h1), pack2(v.z - h2, v.w - h3) };
        __nv_bfloat16* row = Aext + (size_t)(t0 * 128 + r) * KA + c4 * 4;
        *(uint2*)(row)       = uh;   // Ah
        *(uint2*)(row + 128) = ul;   // Al
    }
}

// ---------------------------------------------------------------------------
// convW (all 4 combos in one launch, grid.y = combo):
// fp32 W-half [128 k][256 n] -> Wext [256 n][384] = [Wh | Wl | Wh]
// ---------------------------------------------------------------------------
__global__ __launch_bounds__(256)
void convW_kernel(const float* __restrict__ Wc, const float* __restrict__ Wb,
                  __nv_bfloat16* __restrict__ wext) {
    const int combo = blockIdx.y;
    const float* Wsrc = ((combo < 2) ? Wc : Wb) + (size_t)(combo & 1) * IN_DIM * HID;
    __nv_bfloat16* Wext = wext + (size_t)combo * HID * KEXT;
    for (int idx = blockIdx.x * 256 + threadIdx.x; idx < HID * IN_DIM;
         idx += gridDim.x * 256) {
        const int n = idx >> 7, k = idx & 127;
        const float x = Wsrc[(size_t)k * HID + n];
        const __nv_bfloat16 h = __float2bfloat16_rn(x);
        const float l = x - __bfloat162float(h);
        __nv_bfloat16* row = Wext + (size_t)n * KEXT;
        row[k]       = h;
        row[128 + k] = __float2bfloat16_rn(l);
        row[256 + k] = h;
    }
}

// ---------------------------------------------------------------------------
// persistent fused gemm: grid = min(ntiles,148); each CTA loops tiles with
// stride gridDim.x. A double-buffered ACROSS tiles (prefetch at chunk 0),
// B double-buffered across the 12 chunk iterations (2 tasks x 6 chunks).
// smem: A0 64KB | A1 64KB | B0 32KB | B1 32KB = 192KB.
// ---------------------------------------------------------------------------
#define KC 64
#define SMA 65536
#define SM_B_OFF (2 * SMA)
#define GEMM_SMEM (SM_B_OFF + 2 * 32768)

__device__ __forceinline__ void ldsm4(uint32_t* r, uint32_t a) {
    asm volatile("ldmatrix.sync.aligned.m8n8.x4.shared.b16 {%0,%1,%2,%3}, [%4];"
                 : "=r"(r[0]), "=r"(r[1]), "=r"(r[2]), "=r"(r[3]) : "r"(a));
}
__device__ __forceinline__ void mma16816(float* d, const uint32_t* a, const uint32_t* b) {
    asm volatile("mma.sync.aligned.m16n8k16.row.col.f32.bf16.bf16.f32 "
                 "{%0,%1,%2,%3}, {%4,%5,%6,%7}, {%8,%9}, {%0,%1,%2,%3};"
                 : "+f"(d[0]), "+f"(d[1]), "+f"(d[2]), "+f"(d[3])
                 : "r"(a[0]), "r"(a[1]), "r"(a[2]), "r"(a[3]), "r"(b[0]), "r"(b[1]));
}

__global__ __launch_bounds__(512, 1)
void gemm_kernel(const __nv_bfloat16* __restrict__ Aext, int ntiles, int N,
                 const __nv_bfloat16* __restrict__ W0,
                 const __nv_bfloat16* __restrict__ W1,
                 float* __restrict__ P0, float* __restrict__ P1) {
    extern __shared__ __align__(1024) unsigned char sm[];
    const uint32_t sbase = smem_u32(sm);
    const int tid  = threadIdx.x;
    const int lane = tid & 31;
    const int wid  = tid >> 5;
    const int wm   = wid & 3;
    const int wn   = wid >> 2;

    // B chunk for iteration it (0..11): task = it/6, chunk = it%6, parity it&1
    auto issue_b = [&](int it) {
        const char* Bb = (const char*)((it < 6) ? W0 : W1);
        const int c = it % 6;
        const uint32_t sb = sbase + SM_B_OFF + (uint32_t)(it & 1) * 32768;
        #pragma unroll
        for (int i = 0; i < 4; i++) {
            const int idx = tid + i * 512;
            const int r = idx >> 3, s = idx & 7;
            const size_t go = (size_t)r * (KEXT * 2) + c * (KC * 2) + s * 16;
            const uint32_t so = swz((uint32_t)(r * 128 + s * 16));
            asm volatile("cp.async.cg.shared.global [%0], [%1], 16;"
                         :: "r"(sb + so), "l"(Bb + go) : "memory");
        }
        asm volatile("cp.async.commit_group;" ::: "memory");
    };
    // A tile t -> buffer buf (4 k-chunks of 16KB, swizzled)
    auto issue_a = [&](int t, int buf) {
        const char* Ab = (const char*)(Aext + (size_t)t * 128 * KA);
        const uint32_t sa = sbase + (uint32_t)buf * SMA;
        #pragma unroll
        for (int i = 0; i < 8; i++) {
            const int idx = tid + i * 512;
            const int r = idx >> 5, ck = (idx >> 3) & 3, s = idx & 7;
            const size_t go = (size_t)r * (KA * 2) + ck * (KC * 2) + s * 16;
            const uint32_t so = (uint32_t)(ck * 16384) + swz((uint32_t)(r * 128 + s * 16));
            asm volatile("cp.async.cg.shared.global [%0], [%1], 16;"
                         :: "r"(sa + so), "l"(Ab + go) : "memory");
        }
        asm volatile("cp.async.commit_group;" ::: "memory");
    };

    float acc[2][8][4];
    #pragma unroll
    for (int mt = 0; mt < 2; mt++)
        #pragma unroll
        for (int nt = 0; nt < 8; nt++)
            #pragma unroll
            for (int j = 0; j < 4; j++) acc[mt][nt][j] = 0.f;

    const int t0 = blockIdx.x;
    if (t0 >= ntiles) return;

    issue_a(t0, 0);     // group: A(t0)
    issue_b(0);         // group: B(0)

    const int amap[6] = {0, 1, 0, 1, 2, 3};
    int ab = 0;

    for (int t = t0; t < ntiles; t += gridDim.x) {
        const int tnext = t + gridDim.x;
        const bool a_iss = (tnext < ntiles);

        #pragma unroll
        for (int it = 0; it < 12; it++) {
            const bool last_all = (it == 11) && !a_iss;
            if (!last_all) issue_b((it + 1) % 12);
            if (it == 0 && a_iss) issue_a(tnext, ab ^ 1);

            // wait so that B(it) (and at it==0 also A(t)) are complete
            if (last_all)                cpwait<0>();
            else if (it < 2 && a_iss)    cpwait<2>();   // newest 2 = {B(it+1), A(next)}
            else                         cpwait<1>();   // newest 1 = B(it+1)
            __syncthreads();

            const uint32_t sa = sbase + (uint32_t)ab * SMA + (uint32_t)(amap[it % 6] * 16384);
            const uint32_t sb = sbase + SM_B_OFF + (uint32_t)(it & 1) * 32768;

            #pragma unroll
            for (int ks = 0; ks < KC / 16; ks++) {
                uint32_t af[2][4];
                #pragma unroll
                for (int mt = 0; mt < 2; mt++) {
                    const int row = wm * 32 + mt * 16 + (lane & 15);
                    const uint32_t off = (uint32_t)(row * 128 + ks * 32 + (lane >> 4) * 16);
                    ldsm4(af[mt], sa + swz(off));
                }
                uint32_t bfr[8][2];
                #pragma unroll
                for (int ntp = 0; ntp < 4; ntp++) {
                    const int nrow = wn * 64 + ntp * 16 + ((lane >> 4) << 3) + (lane & 7);
                    const uint32_t off = (uint32_t)(nrow * 128 + ks * 32 + ((lane >> 3) & 1) * 16);
                    uint32_t r4[4];
                    ldsm4(r4, sb + swz(off));
                    bfr[2 * ntp][0] = r4[0]; bfr[2 * ntp][1] = r4[1];
                    bfr[2 * ntp + 1][0] = r4[2]; bfr[2 * ntp + 1][1] = r4[3];
                }
                #pragma unroll
                for (int mt = 0; mt < 2; mt++)
                    #pragma unroll
                    for (int nt = 0; nt < 8; nt++)
                        mma16816(acc[mt][nt], af[mt], bfr[nt]);
            }
            __syncthreads();

            if (it == 5 || it == 11) {
                float* Pt = (it == 5) ? P0 : P1;
                const int rb = t * 128 + wm * 32 + (lane >> 2);
                const int cb = wn * 64 + (lane & 3) * 2;
                #pragma unroll
                for (int mt = 0; mt < 2; mt++) {
                    #pragma unroll
                    for (int half = 0; half < 2; half++) {
                        const int r = rb + mt * 16 + half * 8;
                        if (r < N) {
                            float* dst = Pt + (size_t)r * HID + cb;
                            #pragma unroll
                            for (int nt = 0; nt < 8; nt++) {
                                float2 v = { acc[mt][nt][half * 2], acc[mt][nt][half * 2 + 1] };
                                *(float2*)(dst + nt * 8) = v;
                            }
                        }
                    }
                }
                #pragma unroll
                for (int mt = 0; mt < 2; mt++)
                    #pragma unroll
                    for (int nt = 0; nt < 8; nt++)
                        #pragma unroll
                        for (int j = 0; j < 4; j++) acc[mt][nt][j] = 0.f;
            }
        }
        ab ^= 1;
    }
}

// ---------------------------------------------------------------------------
// edge: both tasks in one launch; one warp per edge.
// ---------------------------------------------------------------------------
__global__ __launch_bounds__(256)
void edge_kernel(const int* __restrict__ uc, const int* __restrict__ vc,
                 const int* __restrict__ ub, const int* __restrict__ vb,
                 const float4* __restrict__ Pc, const float4* __restrict__ Qc,
                 const float4* __restrict__ Pb, const float4* __restrict__ Qb,
                 const float4* __restrict__ b1c, const float4* __restrict__ W2c,
                 const float* __restrict__ b2c,
                 const float4* __restrict__ b1b, const float4* __restrict__ W2b,
                 const float* __restrict__ b2b,
                 float* __restrict__ out, int E) {
    const int gw   = (blockIdx.x * blockDim.x + threadIdx.x) >> 5;
    const int lane = threadIdx.x & 31;
    if (gw >= 2 * E) return;
    const bool buys = (gw >= E);
    const int e = buys ? gw - E : gw;

    const int u = __ldg((buys ? ub : uc) + e);
    const int v = __ldg((buys ? vb : vc) + e);
    const float4* pu = (buys ? Pb : Pc) + (size_t)u * (HID / 4);
    const float4* qv = (buys ? Qb : Qc) + (size_t)v * (HID / 4);
    const float4* b1 = buys ? b1b : b1c;
    const float4* W2 = buys ? W2b : W2c;
    const float*  b2 = buys ? b2b : b2c;

    float acc = 0.0f;
    #pragma unroll
    for (int s = 0; s < 2; s++) {
        int j = lane + 32 * s;
        float4 p = pu[j], q = qv[j];
        float4 b = __ldg(b1 + j), w = __ldg(W2 + j);
        acc = fmaf(fmaxf(p.x + q.x + b.x, 0.f), w.x, acc);
        acc = fmaf(fmaxf(p.y + q.y + b.y, 0.f), w.y, acc);
        acc = fmaf(fmaxf(p.z + q.z + b.z, 0.f), w.z, acc);
        acc = fmaf(fmaxf(p.w + q.w + b.w, 0.f), w.w, acc);
    }
    #pragma unroll
    for (int o = 16; o; o >>= 1) acc += __shfl_xor_sync(0xffffffffu, acc, o);
    if (lane == 0) out[gw] = acc + __ldg(b2);
}

// ---------------------------------------------------------------------------
extern "C" void kernel_launch(void* const* d_in, const int* in_sizes, int n_in,
                              void* d_out, int out_size) {
    const float* user_embed = (const float*)d_in[0];
    const float* item_embed = (const float*)d_in[1];
    const int*   u_clicks   = (const int*)  d_in[2];
    const int*   v_clicks   = (const int*)  d_in[3];
    const int*   u_buys     = (const int*)  d_in[4];
    const int*   v_buys     = (const int*)  d_in[5];
    const float* W1_clicks  = (const float*)d_in[6];
    const float* b1_clicks  = (const float*)d_in[7];
    const float* W2_clicks  = (const float*)d_in[8];
    const float* b2_clicks  = (const float*)d_in[9];
    const float* W1_buys    = (const float*)d_in[10];
    const float* b1_buys    = (const float*)d_in[11];
    const float* W2_buys    = (const float*)d_in[12];
    const float* b2_buys    = (const float*)d_in[13];

    const int E = in_sizes[2];
    float* out = (float*)d_out;

    float* scratch = nullptr;
    cudaGetSymbolAddress((void**)&scratch, g_scratch);
    float* Pc = scratch;
    float* Qc = Pc + P_ELEMS;
    float* Pb = Qc + Q_ELEMS;
    float* Qb = Pb + P_ELEMS;

    __nv_bfloat16 *aext_u = nullptr, *aext_i = nullptr, *wext = nullptr;
    cudaGetSymbolAddress((void**)&aext_u, g_aext_u);
    cudaGetSymbolAddress((void**)&aext_i, g_aext_i);
    cudaGetSymbolAddress((void**)&wext,   g_wext);

    static bool attr_set = false;
    if (!attr_set) {
        cudaFuncSetAttribute(gemm_kernel,
                             cudaFuncAttributeMaxDynamicSharedMemorySize, GEMM_SMEM);
        attr_set = true;
    }

    const size_t wstride = (size_t)HID * KEXT;
    convW_kernel<<<dim3(16, 4), 256>>>(W1_clicks, W1_buys, wext);
    convA_kernel<<<NTILE_U, 256>>>(user_embed, NU, aext_u);
    convA_kernel<<<NTILE_I, 256>>>(item_embed, NI, aext_i);

    const int gU = NTILE_U < 148 ? NTILE_U : 148;
    const int gI = NTILE_I < 148 ? NTILE_I : 148;
    gemm_kernel<<<gU, 512, GEMM_SMEM>>>(aext_u, NTILE_U, NU,
                                        wext + 0 * wstride, wext + 2 * wstride,
                                        Pc, Pb);
    gemm_kernel<<<gI, 512, GEMM_SMEM>>>(aext_i, NTILE_I, NI,
                                        wext + 1 * wstride, wext + 3 * wstride,
                                        Qc, Qb);

    const int eb = (2 * E + 7) / 8;
    edge_kernel<<<eb, 256>>>(u_clicks, v_clicks, u_buys, v_buys,
                             (const float4*)Pc, (const float4*)Qc,
                             (const float4*)Pb, (const float4*)Qb,
                             (const float4*)b1_clicks, (const float4*)W2_clicks, b2_clicks,
                             (const float4*)b1_buys, (const float4*)W2_buys, b2_buys,
                             out, E);
}

// round 7
// speedup vs baseline: 2.9124x; 1.0694x over previous
#include <cuda_runtime.h>
#include <cuda_bf16.h>
#include <cuda_fp16.h>
#include <cstdint>

#define IN_DIM 128
#define HID    256
#define NU 100000
#define NI 200000
#define NTILE_U ((NU + 127) / 128)   // 782
#define NTILE_I ((NI + 127) / 128)   // 1563
#define KA   256                     // A: [Ah | Al]
#define KEXT 384                     // B: [Wh ; Wl ; Wh]

#define P_ELEMS (100000u * 256u)
#define Q_ELEMS (200000u * 256u)
// fp16 tables: Pc, Qc, Pb, Qb
__device__ __half g_tab[2u * (P_ELEMS + Q_ELEMS)];

__device__ __align__(16) __nv_bfloat16 g_aext_u[(size_t)NTILE_U * 128 * KA];
__device__ __align__(16) __nv_bfloat16 g_aext_i[(size_t)NTILE_I * 128 * KA];
__device__ __align__(16) __nv_bfloat16 g_wext[4][HID * KEXT];   // [n][kext]

// ---------------------------------------------------------------------------
__device__ __forceinline__ uint32_t smem_u32(const void* p) {
    uint32_t a;
    asm("{ .reg .u64 t; cvta.to.shared.u64 t, %1; cvt.u32.u64 %0, t; }"
        : "=r"(a) : "l"(p));
    return a;
}
__device__ __forceinline__ uint32_t swz(uint32_t o) { return o ^ ((o >> 3) & 0x70); }
__device__ __forceinline__ uint32_t pack2(float a, float b) {
    __nv_bfloat162 t = __floats2bfloat162_rn(a, b);
    return *(uint32_t*)&t;
}
template <int N>
__device__ __forceinline__ void cpwait() {
    asm volatile("cp.async.wait_group %0;" :: "n"(N) : "memory");
}

// ---------------------------------------------------------------------------
// convA: fp32 A[N,128] -> Aext[tiles*128, 256] bf16 row-major = [Ah | Al]
// ---------------------------------------------------------------------------
__global__ __launch_bounds__(256)
void convA_kernel(const float* __restrict__ A, int N, __nv_bfloat16* __restrict__ Aext) {
    const int t0 = blockIdx.x;
    for (int idx = threadIdx.x; idx < 128 * 32; idx += 256) {
        const int r = idx >> 5, c4 = idx & 31;
        const int rg = t0 * 128 + r;
        float4 v = make_float4(0.f, 0.f, 0.f, 0.f);
        if (rg < N) v = *(const float4*)(A + (size_t)rg * IN_DIM + c4 * 4);
        float h0 = __bfloat162float(__float2bfloat16_rn(v.x));
        float h1 = __bfloat162float(__float2bfloat16_rn(v.y));
        float h2 = __bfloat162float(__float2bfloat16_rn(v.z));
        float h3 = __bfloat162float(__float2bfloat16_rn(v.w));
        uint2 uh = { pack2(h0, h1), pack2(h2, h3) };
        uint2 ul = { pack2(v.x - h0, v.y - h1), pack2(v.z - h2, v.w - h3) };
        __nv_bfloat16* row = Aext + (size_t)(t0 * 128 + r) * KA + c4 * 4;
        *(uint2*)(row)       = uh;   // Ah
        *(uint2*)(row + 128) = ul;   // Al
    }
}

// ---------------------------------------------------------------------------
// convW (4 combos in one launch): W-half [128 k][256 n] -> [Wh | Wl | Wh]
// ---------------------------------------------------------------------------
__global__ __launch_bounds__(256)
void convW_kernel(const float* __restrict__ Wc, const float* __restrict__ Wb,
                  __nv_bfloat16* __restrict__ wext) {
    const int combo = blockIdx.y;
    const float* Wsrc = ((combo < 2) ? Wc : Wb) + (size_t)(combo & 1) * IN_DIM * HID;
    __nv_bfloat16* Wext = wext + (size_t)combo * HID * KEXT;
    for (int idx = blockIdx.x * 256 + threadIdx.x; idx < HID * IN_DIM;
         idx += gridDim.x * 256) {
        const int n = idx >> 7, k = idx & 127;
        const float x = Wsrc[(size_t)k * HID + n];
        const __nv_bfloat16 h = __float2bfloat16_rn(x);
        const float l = x - __bfloat162float(h);
        __nv_bfloat16* row = Wext + (size_t)n * KEXT;
        row[k]       = h;
        row[128 + k] = __float2bfloat16_rn(l);
        row[256 + k] = h;
    }
}

// ---------------------------------------------------------------------------
// persistent fused gemm. Epilogue: +b1, convert to fp16, store to P tables.
// smem: A0 64KB | A1 64KB | B0 32KB | B1 32KB = 192KB.
// ---------------------------------------------------------------------------
#define KC 64
#define SMA 65536
#define SM_B_OFF (2 * SMA)
#define GEMM_SMEM (SM_B_OFF + 2 * 32768)

__device__ __forceinline__ void ldsm4(uint32_t* r, uint32_t a) {
    asm volatile("ldmatrix.sync.aligned.m8n8.x4.shared.b16 {%0,%1,%2,%3}, [%4];"
                 : "=r"(r[0]), "=r"(r[1]), "=r"(r[2]), "=r"(r[3]) : "r"(a));
}
__device__ __forceinline__ void mma16816(float* d, const uint32_t* a, const uint32_t* b) {
    asm volatile("mma.sync.aligned.m16n8k16.row.col.f32.bf16.bf16.f32 "
                 "{%0,%1,%2,%3}, {%4,%5,%6,%7}, {%8,%9}, {%0,%1,%2,%3};"
                 : "+f"(d[0]), "+f"(d[1]), "+f"(d[2]), "+f"(d[3])
                 : "r"(a[0]), "r"(a[1]), "r"(a[2]), "r"(a[3]), "r"(b[0]), "r"(b[1]));
}

__global__ __launch_bounds__(512, 1)
void gemm_kernel(const __nv_bfloat16* __restrict__ Aext, int ntiles, int N,
                 const __nv_bfloat16* __restrict__ W0,
                 const __nv_bfloat16* __restrict__ W1,
                 const float* __restrict__ b1_0, const float* __restrict__ b1_1,
                 __half* __restrict__ P0, __half* __restrict__ P1) {
    extern __shared__ __align__(1024) unsigned char sm[];
    const uint32_t sbase = smem_u32(sm);
    const int tid  = threadIdx.x;
    const int lane = tid & 31;
    const int wid  = tid >> 5;
    const int wm   = wid & 3;
    const int wn   = wid >> 2;

    auto issue_b = [&](int it) {
        const char* Bb = (const char*)((it < 6) ? W0 : W1);
        const int c = it % 6;
        const uint32_t sb = sbase + SM_B_OFF + (uint32_t)(it & 1) * 32768;
        #pragma unroll
        for (int i = 0; i < 4; i++) {
            const int idx = tid + i * 512;
            const int r = idx >> 3, s = idx & 7;
            const size_t go = (size_t)r * (KEXT * 2) + c * (KC * 2) + s * 16;
            const uint32_t so = swz((uint32_t)(r * 128 + s * 16));
            asm volatile("cp.async.cg.shared.global [%0], [%1], 16;"
                         :: "r"(sb + so), "l"(Bb + go) : "memory");
        }
        asm volatile("cp.async.commit_group;" ::: "memory");
    };
    auto issue_a = [&](int t, int buf) {
        const char* Ab = (const char*)(Aext + (size_t)t * 128 * KA);
        const uint32_t sa = sbase + (uint32_t)buf * SMA;
        #pragma unroll
        for (int i = 0; i < 8; i++) {
            const int idx = tid + i * 512;
            const int r = idx >> 5, ck = (idx >> 3) & 3, s = idx & 7;
            const size_t go = (size_t)r * (KA * 2) + ck * (KC * 2) + s * 16;
            const uint32_t so = (uint32_t)(ck * 16384) + swz((uint32_t)(r * 128 + s * 16));
            asm volatile("cp.async.cg.shared.global [%0], [%1], 16;"
                         :: "r"(sa + so), "l"(Ab + go) : "memory");
        }
        asm volatile("cp.async.commit_group;" ::: "memory");
    };

    float acc[2][8][4];
    #pragma unroll
    for (int mt = 0; mt < 2; mt++)
        #pragma unroll
        for (int nt = 0; nt < 8; nt++)
            #pragma unroll
            for (int j = 0; j < 4; j++) acc[mt][nt][j] = 0.f;

    const int t0 = blockIdx.x;
    if (t0 >= ntiles) return;

    issue_a(t0, 0);
    issue_b(0);

    const int amap[6] = {0, 1, 0, 1, 2, 3};
    int ab = 0;

    for (int t = t0; t < ntiles; t += gridDim.x) {
        const int tnext = t + gridDim.x;
        const bool a_iss = (tnext < ntiles);

        #pragma unroll
        for (int it = 0; it < 12; it++) {
            const bool last_all = (it == 11) && !a_iss;
            if (!last_all) issue_b((it + 1) % 12);
            if (it == 0 && a_iss) issue_a(tnext, ab ^ 1);

            if (last_all)                cpwait<0>();
            else if (it < 2 && a_iss)    cpwait<2>();
            else                         cpwait<1>();
            __syncthreads();

            const uint32_t sa = sbase + (uint32_t)ab * SMA + (uint32_t)(amap[it % 6] * 16384);
            const uint32_t sb = sbase + SM_B_OFF + (uint32_t)(it & 1) * 32768;

            #pragma unroll
            for (int ks = 0; ks < KC / 16; ks++) {
                uint32_t af[2][4];
                #pragma unroll
                for (int mt = 0; mt < 2; mt++) {
                    const int row = wm * 32 + mt * 16 + (lane & 15);
                    const uint32_t off = (uint32_t)(row * 128 + ks * 32 + (lane >> 4) * 16);
                    ldsm4(af[mt], sa + swz(off));
                }
                uint32_t bfr[8][2];
                #pragma unroll
                for (int ntp = 0; ntp < 4; ntp++) {
                    const int nrow = wn * 64 + ntp * 16 + ((lane >> 4) << 3) + (lane & 7);
                    const uint32_t off = (uint32_t)(nrow * 128 + ks * 32 + ((lane >> 3) & 1) * 16);
                    uint32_t r4[4];
                    ldsm4(r4, sb + swz(off));
                    bfr[2 * ntp][0] = r4[0]; bfr[2 * ntp][1] = r4[1];
                    bfr[2 * ntp + 1][0] = r4[2]; bfr[2 * ntp + 1][1] = r4[3];
                }
                #pragma unroll
                for (int mt = 0; mt < 2; mt++)
                    #pragma unroll
                    for (int nt = 0; nt < 8; nt++)
                        mma16816(acc[mt][nt], af[mt], bfr[nt]);
            }
            __syncthreads();

            if (it == 5 || it == 11) {
                __half* Pt = (it == 5) ? P0 : P1;
                const float* b1 = (it == 5) ? b1_0 : b1_1;
                const int rb = t * 128 + wm * 32 + (lane >> 2);
                const int cb = wn * 64 + (lane & 3) * 2;
                #pragma unroll
                for (int mt = 0; mt < 2; mt++) {
                    #pragma unroll
                    for (int hf = 0; hf < 2; hf++) {
                        const int r = rb + mt * 16 + hf * 8;
                        if (r < N) {
                            __half* dst = Pt + (size_t)r * HID + cb;
                            #pragma unroll
                            for (int nt = 0; nt < 8; nt++) {
                                const int c = cb + nt * 8;
                                float a0 = acc[mt][nt][hf * 2]     + __ldg(b1 + c);
                                float a1 = acc[mt][nt][hf * 2 + 1] + __ldg(b1 + c + 1);
                                *(__half2*)(dst + nt * 8) = __floats2half2_rn(a0, a1);
                            }
                        }
                    }
                }
                #pragma unroll
                for (int mt = 0; mt < 2; mt++)
                    #pragma unroll
                    for (int nt = 0; nt < 8; nt++)
                        #pragma unroll
                        for (int j = 0; j < 4; j++) acc[mt][nt][j] = 0.f;
            }
        }
        ab ^= 1;
    }
}

// ---------------------------------------------------------------------------
// edge: both tasks, one warp per edge, fp16 tables (b1 pre-folded into P).
// Each lane: 8 hidden units = one uint4 from P and one from Q.
// ---------------------------------------------------------------------------
__global__ __launch_bounds__(256)
void edge_kernel(const int* __restrict__ uc, const int* __restrict__ vc,
                 const int* __restrict__ ub, const int* __restrict__ vb,
                 const __half* __restrict__ Pc, const __half* __restrict__ Qc,
                 const __half* __restrict__ Pb, const __half* __restrict__ Qb,
                 const float4* __restrict__ W2c, const float* __restrict__ b2c,
                 const float4* __restrict__ W2b, const float* __restrict__ b2b,
                 float* __restrict__ out, int E) {
    const int gw   = (blockIdx.x * blockDim.x + threadIdx.x) >> 5;
    const int lane = threadIdx.x & 31;
    if (gw >= 2 * E) return;
    const bool buys = (gw >= E);
    const int e = buys ? gw - E : gw;

    const int u = __ldg((buys ? ub : uc) + e);
    const int v = __ldg((buys ? vb : vc) + e);
    const __half* pu = (buys ? Pb : Pc) + (size_t)u * HID;
    const __half* qv = (buys ? Qb : Qc) + (size_t)v * HID;
    const float4* W2 = buys ? W2b : W2c;
    const float*  b2 = buys ? b2b : b2c;

    uint4 pr = *(const uint4*)(pu + lane * 8);
    uint4 qr = *(const uint4*)(qv + lane * 8);
    float4 w0 = __ldg(W2 + lane * 2);
    float4 w1 = __ldg(W2 + lane * 2 + 1);

    const __half2* p2 = (const __half2*)&pr;
    const __half2* q2 = (const __half2*)&qr;
    float acc = 0.0f;
    float w[8] = { w0.x, w0.y, w0.z, w0.w, w1.x, w1.y, w1.z, w1.w };
    #pragma unroll
    for (int i = 0; i < 4; i++) {
        float2 pf = __half22float2(p2[i]);
        float2 qf = __half22float2(q2[i]);
        acc = fmaf(fmaxf(pf.x + qf.x, 0.f), w[2 * i],     acc);
        acc = fmaf(fmaxf(pf.y + qf.y, 0.f), w[2 * i + 1], acc);
    }
    #pragma unroll
    for (int o = 16; o; o >>= 1) acc += __shfl_xor_sync(0xffffffffu, acc, o);
    if (lane == 0) out[gw] = acc + __ldg(b2);
}

// ---------------------------------------------------------------------------
extern "C" void kernel_launch(void* const* d_in, const int* in_sizes, int n_in,
                              void* d_out, int out_size) {
    const float* user_embed = (const float*)d_in[0];
    const float* item_embed = (const float*)d_in[1];
    const int*   u_clicks   = (const int*)  d_in[2];
    const int*   v_clicks   = (const int*)  d_in[3];
    const int*   u_buys     = (const int*)  d_in[4];
    const int*   v_buys     = (const int*)  d_in[5];
    const float* W1_clicks  = (const float*)d_in[6];
    const float* b1_clicks  = (const float*)d_in[7];
    const float* W2_clicks  = (const float*)d_in[8];
    const float* b2_clicks  = (const float*)d_in[9];
    const float* W1_buys    = (const float*)d_in[10];
    const float* b1_buys    = (const float*)d_in[11];
    const float* W2_buys    = (const float*)d_in[12];
    const float* b2_buys    = (const float*)d_in[13];

    const int E = in_sizes[2];
    float* out = (float*)d_out;

    __half* tab = nullptr;
    cudaGetSymbolAddress((void**)&tab, g_tab);
    __half* Pc = tab;
    __half* Qc = Pc + P_ELEMS;
    __half* Pb = Qc + Q_ELEMS;
    __half* Qb = Pb + P_ELEMS;

    __nv_bfloat16 *aext_u = nullptr, *aext_i = nullptr, *wext = nullptr;
    cudaGetSymbolAddress((void**)&aext_u, g_aext_u);
    cudaGetSymbolAddress((void**)&aext_i, g_aext_i);
    cudaGetSymbolAddress((void**)&wext,   g_wext);

    static bool attr_set = false;
    if (!attr_set) {
        cudaFuncSetAttribute(gemm_kernel,
                             cudaFuncAttributeMaxDynamicSharedMemorySize, GEMM_SMEM);
        attr_set = true;
    }

    const size_t wstride = (size_t)HID * KEXT;
    convW_kernel<<<dim3(16, 4), 256>>>(W1_clicks, W1_buys, wext);
    convA_kernel<<<NTILE_U, 256>>>(user_embed, NU, aext_u);
    convA_kernel<<<NTILE_I, 256>>>(item_embed, NI, aext_i);

    const int gU = NTILE_U < 148 ? NTILE_U : 148;
    const int gI = NTILE_I < 148 ? NTILE_I : 148;
    gemm_kernel<<<gU, 512, GEMM_SMEM>>>(aext_u, NTILE_U, NU,
                                        wext + 0 * wstride, wext + 2 * wstride,
                                        b1_clicks, b1_buys, Pc, Pb);
    gemm_kernel<<<gI, 512, GEMM_SMEM>>>(aext_i, NTILE_I, NI,
                                        wext + 1 * wstride, wext + 3 * wstride,
                                        b1_clicks, b1_buys, Qc, Qb);

    const int eb = (2 * E + 7) / 8;
    edge_kernel<<<eb, 256>>>(u_clicks, v_clicks, u_buys, v_buys,
                             Pc, Qc, Pb, Qb,
                             (const float4*)W2_clicks, b2_clicks,
                             (const float4*)W2_buys, b2_buys,
                             out, E);
}